// round 6
// baseline (speedup 1.0000x reference)
#include <cuda_runtime.h>
#include <math.h>

// Problem constants
#define NB 4          // batch
#define CC 512        // channels C
#define KPD 512       // key planes
#define NP 4096       // H*W
#define MP 4096       // HS*WS

// ----------------------------------------------------------------------------
// Device-global scratch (alloc-free per harness rules)
// ----------------------------------------------------------------------------
__device__ float g_F[(size_t)NB * NP * KPD];   // [b, n, k]   32 MB
__device__ float g_G[(size_t)NB * MP * KPD];   // [b, m, k]   32 MB
__device__ float g_H[(size_t)NB * MP * CC];    // [b, m, c]   32 MB
__device__ float g_S[(size_t)NB * NP * MP];    // [b, n, m]  256 MB

// ----------------------------------------------------------------------------
// Kernel 1: 1x1 conv as GEMM.
//   Out[b, i, j] = sum_k X[b, k, i] * W[j, k] + bias[j]
// X: [B, K, I] (channel-major, pixels contiguous), W: [J, K] row-major.
// I = 4096, K = 512, J = 512. Tile 128x128x8, 256 threads, 8x8 micro.
// dest: 0 -> g_F, 1 -> g_G, 2 -> g_H
// ----------------------------------------------------------------------------
__global__ void __launch_bounds__(256)
conv1x1_gemm(const float* __restrict__ X, const float* __restrict__ W,
             const float* __restrict__ bias, int dest)
{
    const int I = NP, K = KPD, J = KPD;
    __shared__ float As[8][128];
    __shared__ float Bs[8][129];

    int b  = blockIdx.z;
    int i0 = blockIdx.x * 128;
    int j0 = blockIdx.y * 128;
    const float* Xb = X + (size_t)b * K * I;
    float* Out = (dest == 0) ? g_F : (dest == 1) ? g_G : g_H;
    float* Outb = Out + (size_t)b * I * J;

    int tid = threadIdx.x;
    int tx = tid & 15, ty = tid >> 4;

    float acc[8][8];
#pragma unroll
    for (int ii = 0; ii < 8; ii++)
#pragma unroll
        for (int jj = 0; jj < 8; jj++) acc[ii][jj] = 0.f;

    for (int kk = 0; kk < K; kk += 8) {
        // A tile: As[k][i] = X[b, kk+k, i0+i]  (coalesced over i)
#pragma unroll
        for (int p = 0; p < 4; p++) {
            int e = tid + p * 256;
            int i = e & 127, k = e >> 7;
            As[k][i] = Xb[(size_t)(kk + k) * I + i0 + i];
        }
        // B tile: Bs[k][j] = W[(j0+j)*K + kk + k] (W is tiny, L2-resident)
#pragma unroll
        for (int p = 0; p < 4; p++) {
            int e = tid + p * 256;
            int k = e & 7, j = e >> 3;
            Bs[k][j] = W[(size_t)(j0 + j) * K + kk + k];
        }
        __syncthreads();
#pragma unroll
        for (int k = 0; k < 8; k++) {
            float a[8], bb[8];
#pragma unroll
            for (int ii = 0; ii < 8; ii++) a[ii] = As[k][ty + ii * 16];
#pragma unroll
            for (int jj = 0; jj < 8; jj++) bb[jj] = Bs[k][tx + jj * 16];
#pragma unroll
            for (int ii = 0; ii < 8; ii++)
#pragma unroll
                for (int jj = 0; jj < 8; jj++)
                    acc[ii][jj] += a[ii] * bb[jj];
        }
        __syncthreads();
    }

#pragma unroll
    for (int jj = 0; jj < 8; jj++) {
        float bv = bias[j0 + tx + jj * 16];
#pragma unroll
        for (int ii = 0; ii < 8; ii++) {
            Outb[(size_t)(i0 + ty + ii * 16) * J + (j0 + tx + jj * 16)] =
                acc[ii][jj] + bv;
        }
    }
}

// ----------------------------------------------------------------------------
// Kernel 2: attention logits, NT GEMM.
//   L[b, n, m] = sum_k F[b, n, k] * G[b, m, k]
// Tile 128x128x8.
// ----------------------------------------------------------------------------
__global__ void __launch_bounds__(256)
logits_gemm()
{
    __shared__ float As[8][129];
    __shared__ float Bs[8][129];

    int b  = blockIdx.z;
    int n0 = blockIdx.x * 128;
    int m0 = blockIdx.y * 128;
    const float* Fb = g_F + (size_t)b * NP * KPD;
    const float* Gb = g_G + (size_t)b * MP * KPD;
    float* Sb = g_S + (size_t)b * NP * MP;

    int tid = threadIdx.x;
    int tx = tid & 15, ty = tid >> 4;

    float acc[8][8];
#pragma unroll
    for (int ii = 0; ii < 8; ii++)
#pragma unroll
        for (int jj = 0; jj < 8; jj++) acc[ii][jj] = 0.f;

    for (int kk = 0; kk < KPD; kk += 8) {
        // As[k][i] = F[(n0+i)*KPD + kk+k]; 8-wide (32B) contiguous reads
#pragma unroll
        for (int p = 0; p < 4; p++) {
            int e = tid + p * 256;
            int k = e & 7, i = e >> 3;
            As[k][i] = Fb[(size_t)(n0 + i) * KPD + kk + k];
        }
#pragma unroll
        for (int p = 0; p < 4; p++) {
            int e = tid + p * 256;
            int k = e & 7, j = e >> 3;
            Bs[k][j] = Gb[(size_t)(m0 + j) * KPD + kk + k];
        }
        __syncthreads();
#pragma unroll
        for (int k = 0; k < 8; k++) {
            float a[8], bb[8];
#pragma unroll
            for (int ii = 0; ii < 8; ii++) a[ii] = As[k][ty + ii * 16];
#pragma unroll
            for (int jj = 0; jj < 8; jj++) bb[jj] = Bs[k][tx + jj * 16];
#pragma unroll
            for (int ii = 0; ii < 8; ii++)
#pragma unroll
                for (int jj = 0; jj < 8; jj++)
                    acc[ii][jj] += a[ii] * bb[jj];
        }
        __syncthreads();
    }

#pragma unroll
    for (int ii = 0; ii < 8; ii++)
#pragma unroll
        for (int jj = 0; jj < 8; jj++) {
            Sb[(size_t)(n0 + ty + ii * 16) * MP + (m0 + tx + jj * 16)] =
                acc[ii][jj];
        }
}

// ----------------------------------------------------------------------------
// Kernel 3: row softmax over M, in place in g_S. One block (256 threads) per
// row; 16 elements per thread held in registers.
// ----------------------------------------------------------------------------
__global__ void __launch_bounds__(256)
softmax_rows()
{
    __shared__ float red[256];
    int row = blockIdx.x;                // in [0, NB*NP)
    size_t base = (size_t)row * MP;
    int tid = threadIdx.x;

    float v[16];
    float lmax = -1e30f;
#pragma unroll
    for (int t = 0; t < 16; t++) {
        v[t] = g_S[base + tid + t * 256];
        lmax = fmaxf(lmax, v[t]);
    }
    red[tid] = lmax;
    __syncthreads();
    for (int s = 128; s > 0; s >>= 1) {
        if (tid < s) red[tid] = fmaxf(red[tid], red[tid + s]);
        __syncthreads();
    }
    float m = red[0];
    __syncthreads();

    float lsum = 0.f;
#pragma unroll
    for (int t = 0; t < 16; t++) {
        v[t] = __expf(v[t] - m);
        lsum += v[t];
    }
    red[tid] = lsum;
    __syncthreads();
    for (int s = 128; s > 0; s >>= 1) {
        if (tid < s) red[tid] += red[tid + s];
        __syncthreads();
    }
    float inv = 1.f / red[0];

#pragma unroll
    for (int t = 0; t < 16; t++)
        g_S[base + tid + t * 256] = v[t] * inv;
}

// ----------------------------------------------------------------------------
// Kernel 4: dual NN GEMM + fused epilogue.
//   mean[n,c] = sum_m S[n,m] * H[m,c]
//   e2[n,c]   = sum_m S[n,m] * H[m,c]^2
//   out[b,c,n] = sqrt(relu(e2 - mean^2)) * c_x[b,c,n] + mean
// Tile 128(n) x 64(c) x 8(m), 256 threads, 8x4 dual micro-tile.
// ----------------------------------------------------------------------------
__global__ void __launch_bounds__(256)
meanstd_gemm(const float* __restrict__ c_x, float* __restrict__ out)
{
    __shared__ float As[8][129];   // S tile
    __shared__ float Bs[8][64];    // H tile

    int b  = blockIdx.z;
    int n0 = blockIdx.x * 128;
    int c0 = blockIdx.y * 64;
    const float* Sb = g_S + (size_t)b * NP * MP;
    const float* Hb = g_H + (size_t)b * MP * CC;

    int tid = threadIdx.x;
    int tx = tid & 15, ty = tid >> 4;

    float am[8][4], ae[8][4];
#pragma unroll
    for (int ii = 0; ii < 8; ii++)
#pragma unroll
        for (int jj = 0; jj < 4; jj++) { am[ii][jj] = 0.f; ae[ii][jj] = 0.f; }

    for (int mm = 0; mm < MP; mm += 8) {
        // S tile: As[k][i] = S[(n0+i)*MP + mm+k]; contiguous 8-wide over k
#pragma unroll
        for (int p = 0; p < 4; p++) {
            int e = tid + p * 256;
            int k = e & 7, i = e >> 3;
            As[k][i] = Sb[(size_t)(n0 + i) * MP + mm + k];
        }
        // H tile: Bs[k][j] = H[(mm+k)*CC + c0+j]; 64-wide coalesced
#pragma unroll
        for (int p = 0; p < 2; p++) {
            int e = tid + p * 256;
            int j = e & 63, k = e >> 6;
            Bs[k][j] = Hb[(size_t)(mm + k) * CC + c0 + j];
        }
        __syncthreads();
#pragma unroll
        for (int k = 0; k < 8; k++) {
            float a[8], bb[4], b2[4];
#pragma unroll
            for (int ii = 0; ii < 8; ii++) a[ii] = As[k][ty + ii * 16];
#pragma unroll
            for (int jj = 0; jj < 4; jj++) {
                bb[jj] = Bs[k][tx + jj * 16];
                b2[jj] = bb[jj] * bb[jj];
            }
#pragma unroll
            for (int ii = 0; ii < 8; ii++)
#pragma unroll
                for (int jj = 0; jj < 4; jj++) {
                    am[ii][jj] += a[ii] * bb[jj];
                    ae[ii][jj] += a[ii] * b2[jj];
                }
        }
        __syncthreads();
    }

    // Epilogue: std*c_x + mean, written in [b, c, n] layout.
#pragma unroll
    for (int ii = 0; ii < 8; ii++) {
        int n = n0 + ty + ii * 16;
#pragma unroll
        for (int jj = 0; jj < 4; jj++) {
            int c = c0 + tx + jj * 16;
            float mval = am[ii][jj];
            float e2   = ae[ii][jj];
            float sd   = sqrtf(fmaxf(e2 - mval * mval, 0.f));
            size_t idx = ((size_t)b * CC + c) * NP + n;
            out[idx] = sd * c_x[idx] + mval;
        }
    }
}

// ----------------------------------------------------------------------------
// Launch
// ----------------------------------------------------------------------------
extern "C" void kernel_launch(void* const* d_in, const int* in_sizes, int n_in,
                              void* d_out, int out_size)
{
    const float* c_x  = (const float*)d_in[0];
    const float* s_x  = (const float*)d_in[1];
    const float* c_1x = (const float*)d_in[2];
    const float* s_1x = (const float*)d_in[3];
    const float* f_w  = (const float*)d_in[4];
    const float* f_b  = (const float*)d_in[5];
    const float* g_w  = (const float*)d_in[6];
    const float* g_b  = (const float*)d_in[7];
    const float* h_w  = (const float*)d_in[8];
    const float* h_b  = (const float*)d_in[9];
    float* out = (float*)d_out;

    (void)in_sizes; (void)n_in; (void)out_size;

    dim3 gridA(NP / 128, KPD / 128, NB);           // (32, 4, 4)
    conv1x1_gemm<<<gridA, 256>>>(c_1x, f_w, f_b, 0);   // F
    conv1x1_gemm<<<gridA, 256>>>(s_1x, g_w, g_b, 1);   // G
    conv1x1_gemm<<<gridA, 256>>>(s_x,  h_w, h_b, 2);   // Hs

    dim3 gridL(NP / 128, MP / 128, NB);            // (32, 32, 4)
    logits_gemm<<<gridL, 256>>>();

    softmax_rows<<<NB * NP, 256>>>();              // 16384 rows

    dim3 gridM(NP / 128, CC / 64, NB);             // (32, 8, 4)
    meanstd_gemm<<<gridM, 256>>>(c_x, out);
}

// round 7
// speedup vs baseline: 1.0017x; 1.0017x over previous
#include <cuda_runtime.h>
#include <math.h>

// Problem constants
#define NB 4          // batch
#define CC 512        // channels C
#define KPD 512       // key planes
#define NP 4096       // H*W
#define MP 4096       // HS*WS

// ----------------------------------------------------------------------------
// Device-global scratch (alloc-free per harness rules)
// ----------------------------------------------------------------------------
__device__ float g_F[(size_t)NB * NP * KPD];   // [b, n, k]   32 MB
__device__ float g_G[(size_t)NB * MP * KPD];   // [b, m, k]   32 MB
__device__ float g_H[(size_t)NB * MP * CC];    // [b, m, c]   32 MB
__device__ float g_S[(size_t)NB * NP * MP];    // [b, n, m]  256 MB

// ----------------------------------------------------------------------------
// Kernel 1: 1x1 conv as GEMM.
//   Out[b, i, j] = sum_k X[b, k, i] * W[j, k] + bias[j]
// X: [B, K, I] (channel-major, pixels contiguous), W: [J, K] row-major.
// I = 4096, K = 512, J = 512. Tile 128x128x8, 256 threads, 8x8 micro.
// dest: 0 -> g_F, 1 -> g_G, 2 -> g_H
// ----------------------------------------------------------------------------
__global__ void __launch_bounds__(256)
conv1x1_gemm(const float* __restrict__ X, const float* __restrict__ W,
             const float* __restrict__ bias, int dest)
{
    const int I = NP, K = KPD, J = KPD;
    __shared__ float As[8][128];
    __shared__ float Bs[8][129];

    int b  = blockIdx.z;
    int i0 = blockIdx.x * 128;
    int j0 = blockIdx.y * 128;
    const float* Xb = X + (size_t)b * K * I;
    float* Out = (dest == 0) ? g_F : (dest == 1) ? g_G : g_H;
    float* Outb = Out + (size_t)b * I * J;

    int tid = threadIdx.x;
    int tx = tid & 15, ty = tid >> 4;

    float acc[8][8];
#pragma unroll
    for (int ii = 0; ii < 8; ii++)
#pragma unroll
        for (int jj = 0; jj < 8; jj++) acc[ii][jj] = 0.f;

    for (int kk = 0; kk < K; kk += 8) {
        // A tile: As[k][i] = X[b, kk+k, i0+i]  (coalesced over i)
#pragma unroll
        for (int p = 0; p < 4; p++) {
            int e = tid + p * 256;
            int i = e & 127, k = e >> 7;
            As[k][i] = Xb[(size_t)(kk + k) * I + i0 + i];
        }
        // B tile: Bs[k][j] = W[(j0+j)*K + kk + k] (W is tiny, L2-resident)
#pragma unroll
        for (int p = 0; p < 4; p++) {
            int e = tid + p * 256;
            int k = e & 7, j = e >> 3;
            Bs[k][j] = W[(size_t)(j0 + j) * K + kk + k];
        }
        __syncthreads();
#pragma unroll
        for (int k = 0; k < 8; k++) {
            float a[8], bb[8];
#pragma unroll
            for (int ii = 0; ii < 8; ii++) a[ii] = As[k][ty + ii * 16];
#pragma unroll
            for (int jj = 0; jj < 8; jj++) bb[jj] = Bs[k][tx + jj * 16];
#pragma unroll
            for (int ii = 0; ii < 8; ii++)
#pragma unroll
                for (int jj = 0; jj < 8; jj++)
                    acc[ii][jj] += a[ii] * bb[jj];
        }
        __syncthreads();
    }

#pragma unroll
    for (int jj = 0; jj < 8; jj++) {
        float bv = bias[j0 + tx + jj * 16];
#pragma unroll
        for (int ii = 0; ii < 8; ii++) {
            Outb[(size_t)(i0 + ty + ii * 16) * J + (j0 + tx + jj * 16)] =
                acc[ii][jj] + bv;
        }
    }
}

// ----------------------------------------------------------------------------
// Kernel 2: attention logits, NT GEMM.
//   L[b, n, m] = sum_k F[b, n, k] * G[b, m, k]
// Tile 128x128x8.
// ----------------------------------------------------------------------------
__global__ void __launch_bounds__(256)
logits_gemm()
{
    __shared__ float As[8][129];
    __shared__ float Bs[8][129];

    int b  = blockIdx.z;
    int n0 = blockIdx.x * 128;
    int m0 = blockIdx.y * 128;
    const float* Fb = g_F + (size_t)b * NP * KPD;
    const float* Gb = g_G + (size_t)b * MP * KPD;
    float* Sb = g_S + (size_t)b * NP * MP;

    int tid = threadIdx.x;
    int tx = tid & 15, ty = tid >> 4;

    float acc[8][8];
#pragma unroll
    for (int ii = 0; ii < 8; ii++)
#pragma unroll
        for (int jj = 0; jj < 8; jj++) acc[ii][jj] = 0.f;

    for (int kk = 0; kk < KPD; kk += 8) {
        // As[k][i] = F[(n0+i)*KPD + kk+k]; 8-wide (32B) contiguous reads
#pragma unroll
        for (int p = 0; p < 4; p++) {
            int e = tid + p * 256;
            int k = e & 7, i = e >> 3;
            As[k][i] = Fb[(size_t)(n0 + i) * KPD + kk + k];
        }
#pragma unroll
        for (int p = 0; p < 4; p++) {
            int e = tid + p * 256;
            int k = e & 7, j = e >> 3;
            Bs[k][j] = Gb[(size_t)(m0 + j) * KPD + kk + k];
        }
        __syncthreads();
#pragma unroll
        for (int k = 0; k < 8; k++) {
            float a[8], bb[8];
#pragma unroll
            for (int ii = 0; ii < 8; ii++) a[ii] = As[k][ty + ii * 16];
#pragma unroll
            for (int jj = 0; jj < 8; jj++) bb[jj] = Bs[k][tx + jj * 16];
#pragma unroll
            for (int ii = 0; ii < 8; ii++)
#pragma unroll
                for (int jj = 0; jj < 8; jj++)
                    acc[ii][jj] += a[ii] * bb[jj];
        }
        __syncthreads();
    }

#pragma unroll
    for (int ii = 0; ii < 8; ii++)
#pragma unroll
        for (int jj = 0; jj < 8; jj++) {
            Sb[(size_t)(n0 + ty + ii * 16) * MP + (m0 + tx + jj * 16)] =
                acc[ii][jj];
        }
}

// ----------------------------------------------------------------------------
// Kernel 3: row softmax over M, in place in g_S. One block (256 threads) per
// row; 16 elements per thread held in registers.
// ----------------------------------------------------------------------------
__global__ void __launch_bounds__(256)
softmax_rows()
{
    __shared__ float red[256];
    int row = blockIdx.x;                // in [0, NB*NP)
    size_t base = (size_t)row * MP;
    int tid = threadIdx.x;

    float v[16];
    float lmax = -1e30f;
#pragma unroll
    for (int t = 0; t < 16; t++) {
        v[t] = g_S[base + tid + t * 256];
        lmax = fmaxf(lmax, v[t]);
    }
    red[tid] = lmax;
    __syncthreads();
    for (int s = 128; s > 0; s >>= 1) {
        if (tid < s) red[tid] = fmaxf(red[tid], red[tid + s]);
        __syncthreads();
    }
    float m = red[0];
    __syncthreads();

    float lsum = 0.f;
#pragma unroll
    for (int t = 0; t < 16; t++) {
        v[t] = __expf(v[t] - m);
        lsum += v[t];
    }
    red[tid] = lsum;
    __syncthreads();
    for (int s = 128; s > 0; s >>= 1) {
        if (tid < s) red[tid] += red[tid + s];
        __syncthreads();
    }
    float inv = 1.f / red[0];

#pragma unroll
    for (int t = 0; t < 16; t++)
        g_S[base + tid + t * 256] = v[t] * inv;
}

// ----------------------------------------------------------------------------
// Kernel 4: dual NN GEMM + fused epilogue.
//   mean[n,c] = sum_m S[n,m] * H[m,c]
//   e2[n,c]   = sum_m S[n,m] * H[m,c]^2
//   out[b,c,n] = sqrt(relu(e2 - mean^2)) * c_x[b,c,n] + mean
// Tile 128(n) x 64(c) x 8(m), 256 threads, 8x4 dual micro-tile.
// ----------------------------------------------------------------------------
__global__ void __launch_bounds__(256)
meanstd_gemm(const float* __restrict__ c_x, float* __restrict__ out)
{
    __shared__ float As[8][129];   // S tile
    __shared__ float Bs[8][64];    // H tile

    int b  = blockIdx.z;
    int n0 = blockIdx.x * 128;
    int c0 = blockIdx.y * 64;
    const float* Sb = g_S + (size_t)b * NP * MP;
    const float* Hb = g_H + (size_t)b * MP * CC;

    int tid = threadIdx.x;
    int tx = tid & 15, ty = tid >> 4;

    float am[8][4], ae[8][4];
#pragma unroll
    for (int ii = 0; ii < 8; ii++)
#pragma unroll
        for (int jj = 0; jj < 4; jj++) { am[ii][jj] = 0.f; ae[ii][jj] = 0.f; }

    for (int mm = 0; mm < MP; mm += 8) {
        // S tile: As[k][i] = S[(n0+i)*MP + mm+k]; contiguous 8-wide over k
#pragma unroll
        for (int p = 0; p < 4; p++) {
            int e = tid + p * 256;
            int k = e & 7, i = e >> 3;
            As[k][i] = Sb[(size_t)(n0 + i) * MP + mm + k];
        }
        // H tile: Bs[k][j] = H[(mm+k)*CC + c0+j]; 64-wide coalesced
#pragma unroll
        for (int p = 0; p < 2; p++) {
            int e = tid + p * 256;
            int j = e & 63, k = e >> 6;
            Bs[k][j] = Hb[(size_t)(mm + k) * CC + c0 + j];
        }
        __syncthreads();
#pragma unroll
        for (int k = 0; k < 8; k++) {
            float a[8], bb[4], b2[4];
#pragma unroll
            for (int ii = 0; ii < 8; ii++) a[ii] = As[k][ty + ii * 16];
#pragma unroll
            for (int jj = 0; jj < 4; jj++) {
                bb[jj] = Bs[k][tx + jj * 16];
                b2[jj] = bb[jj] * bb[jj];
            }
#pragma unroll
            for (int ii = 0; ii < 8; ii++)
#pragma unroll
                for (int jj = 0; jj < 4; jj++) {
                    am[ii][jj] += a[ii] * bb[jj];
                    ae[ii][jj] += a[ii] * b2[jj];
                }
        }
        __syncthreads();
    }

    // Epilogue: std*c_x + mean, written in [b, c, n] layout.
#pragma unroll
    for (int ii = 0; ii < 8; ii++) {
        int n = n0 + ty + ii * 16;
#pragma unroll
        for (int jj = 0; jj < 4; jj++) {
            int c = c0 + tx + jj * 16;
            float mval = am[ii][jj];
            float e2   = ae[ii][jj];
            float sd   = sqrtf(fmaxf(e2 - mval * mval, 0.f));
            size_t idx = ((size_t)b * CC + c) * NP + n;
            out[idx] = sd * c_x[idx] + mval;
        }
    }
}

// ----------------------------------------------------------------------------
// Launch
// ----------------------------------------------------------------------------
extern "C" void kernel_launch(void* const* d_in, const int* in_sizes, int n_in,
                              void* d_out, int out_size)
{
    const float* c_x  = (const float*)d_in[0];
    const float* s_x  = (const float*)d_in[1];
    const float* c_1x = (const float*)d_in[2];
    const float* s_1x = (const float*)d_in[3];
    const float* f_w  = (const float*)d_in[4];
    const float* f_b  = (const float*)d_in[5];
    const float* g_w  = (const float*)d_in[6];
    const float* g_b  = (const float*)d_in[7];
    const float* h_w  = (const float*)d_in[8];
    const float* h_b  = (const float*)d_in[9];
    float* out = (float*)d_out;

    (void)in_sizes; (void)n_in; (void)out_size;

    dim3 gridA(NP / 128, KPD / 128, NB);           // (32, 4, 4)
    conv1x1_gemm<<<gridA, 256>>>(c_1x, f_w, f_b, 0);   // F
    conv1x1_gemm<<<gridA, 256>>>(s_1x, g_w, g_b, 1);   // G
    conv1x1_gemm<<<gridA, 256>>>(s_x,  h_w, h_b, 2);   // Hs

    dim3 gridL(NP / 128, MP / 128, NB);            // (32, 32, 4)
    logits_gemm<<<gridL, 256>>>();

    softmax_rows<<<NB * NP, 256>>>();              // 16384 rows

    dim3 gridM(NP / 128, CC / 64, NB);             // (32, 8, 4)
    meanstd_gemm<<<gridM, 256>>>(c_x, out);
}